// round 1
// baseline (speedup 1.0000x reference)
#include <cuda_runtime.h>

// Quan2d: quantum conv layer.
// Per image (32x32): 16x16 patches of 4x4, stride 2, zero-padded bottom/right.
// Per patch v[16]: u = U v with U = R2 * Pcnot * R1 (orthogonal), then
// <Z_w> = (sum_s sign_w(s) u_s^2) / (sum_s u_s^2).
//
// CNOT ring permutation (control i -> target (i+1)%4, applied i=0..3):
// new[s] = old[h(s)], h(b0,b1,b2,b3) = (b0^b3, b0^b1^b3, b1^b2, b2^b3)
// (b0 = MSB = wire 0, PennyLane convention). Verified h = F^{-1} of the
// forward bit-update. Table: {0,13,3,14,6,11,5,8,12,1,15,2,10,7,9,4}.

__host__ __device__ constexpr int permIdx(int s) {
    int b0 = (s >> 3) & 1, b1 = (s >> 2) & 1, b2 = (s >> 1) & 1, b3 = s & 1;
    int h0 = b0 ^ b3, h1 = b0 ^ b1 ^ b3, h2 = b1 ^ b2, h3 = b2 ^ b3;
    return (h0 << 3) | (h1 << 2) | (h2 << 1) | h3;
}

__global__ __launch_bounds__(256, 4)
void quan2d_kernel(const float* __restrict__ x,
                   const float* __restrict__ w8,
                   float* __restrict__ out)
{
    // --- per-block trig for the 8 RY angles ---
    __shared__ float2 cs[8];
    if (threadIdx.x < 8) {
        float sv, cv;
        sincosf(0.5f * w8[threadIdx.x], &sv, &cv);
        cs[threadIdx.x] = make_float2(cv, sv);
    }
    __syncthreads();

    const int b  = blockIdx.x;
    const int pr = threadIdx.x >> 4;   // patch row 0..15
    const int pc = threadIdx.x & 15;   // patch col 0..15
    const float* img = x + (size_t)b * 1024;

    // --- load 4x4 patch (row-major), zero-padded at rows/cols >= 32 ---
    // Patch covers rows pr*2..pr*2+3, cols pc*2..pc*2+3.
    // float2 granularity matches the padding boundary exactly.
    float a[16];
    #pragma unroll
    for (int i = 0; i < 4; i++) {
        const int r = pr * 2 + i;
        const bool rok = (r < 32);
        const float2* rowp = (const float2*)(img + r * 32 + pc * 2);
        float2 A = rok ? __ldg(rowp)
                       : make_float2(0.f, 0.f);
        float2 B = (rok && pc < 15) ? __ldg(rowp + 1)
                                    : make_float2(0.f, 0.f);
        a[4 * i + 0] = A.x;
        a[4 * i + 1] = A.y;
        a[4 * i + 2] = B.x;
        a[4 * i + 3] = B.y;
    }

    // --- RY layer 1: wire g acts on bit (8 >> g) ---
    #pragma unroll
    for (int g = 0; g < 4; g++) {
        const float c = cs[g].x, s = cs[g].y;
        const int BIT = 8 >> g;
        #pragma unroll
        for (int lo = 0; lo < 16; lo++) {
            if (lo & BIT) continue;
            const float xx = a[lo], yy = a[lo | BIT];
            a[lo]       = fmaf(c, xx, -s * yy);
            a[lo | BIT] = fmaf(s, xx,  c * yy);
        }
    }

    // --- CNOT ring: compile-time permutation (register renaming) ---
    float t[16];
    #pragma unroll
    for (int s2 = 0; s2 < 16; s2++) t[s2] = a[permIdx(s2)];

    // --- RY layer 2 ---
    #pragma unroll
    for (int g = 0; g < 4; g++) {
        const float c = cs[4 + g].x, s = cs[4 + g].y;
        const int BIT = 8 >> g;
        #pragma unroll
        for (int lo = 0; lo < 16; lo++) {
            if (lo & BIT) continue;
            const float xx = t[lo], yy = t[lo | BIT];
            t[lo]       = fmaf(c, xx, -s * yy);
            t[lo | BIT] = fmaf(s, xx,  c * yy);
        }
    }

    // --- probabilities + signed-sum butterfly ---
    float q[16];
    #pragma unroll
    for (int s2 = 0; s2 < 16; s2++) q[s2] = t[s2] * t[s2];

    // stage over bit0 (value 1) -> wire 3
    float s1[8];
    float e3 = 0.f;
    #pragma unroll
    for (int k = 0; k < 8; k++) {
        s1[k] = q[2 * k] + q[2 * k + 1];
        e3   += (q[2 * k] - q[2 * k + 1]);
    }
    // stage over bit1 (value 2) -> wire 2
    float s2a[4];
    float e2 = 0.f;
    #pragma unroll
    for (int k = 0; k < 4; k++) {
        s2a[k] = s1[2 * k] + s1[2 * k + 1];
        e2    += (s1[2 * k] - s1[2 * k + 1]);
    }
    // stage over bit2 (value 4) -> wire 1
    const float s3a = s2a[0] + s2a[1];
    const float s3b = s2a[2] + s2a[3];
    const float e1  = (s2a[0] - s2a[1]) + (s2a[2] - s2a[3]);
    // stage over bit3 (value 8) -> wire 0
    const float n2 = s3a + s3b;
    const float e0 = s3a - s3b;

    const float rn = __frcp_rn(n2);

    float4 o;
    o.x = e0 * rn;
    o.y = e1 * rn;
    o.z = e2 * rn;
    o.w = e3 * rn;
    ((float4*)out)[(size_t)b * 256 + threadIdx.x] = o;
}

extern "C" void kernel_launch(void* const* d_in, const int* in_sizes, int n_in,
                              void* d_out, int out_size)
{
    const float* x = (const float*)d_in[0];   // [B,1,32,32] fp32
    const float* w = (const float*)d_in[1];   // [1,8] fp32
    const int B = in_sizes[0] / 1024;
    quan2d_kernel<<<B, 256>>>(x, w, (float*)d_out);
}

// round 2
// speedup vs baseline: 1.1202x; 1.1202x over previous
#include <cuda_runtime.h>
#include <cstdint>

// Quan2d, round 2: packed f32x2 version — two horizontally adjacent patches
// (pc=2k, 2k+1) of the same image live in the lo/hi lanes of each f32x2 reg.
// Circuit: u = R2 * Pcnot * R1 * v (orthogonal), <Z_w> = signed sums of u^2 / |u|^2.
// CNOT ring permutation h: {0,13,3,14,6,11,5,8,12,1,15,2,10,7,9,4}.

__host__ __device__ constexpr int permIdx(int s) {
    int b0 = (s >> 3) & 1, b1 = (s >> 2) & 1, b2 = (s >> 1) & 1, b3 = s & 1;
    int h0 = b0 ^ b3, h1 = b0 ^ b1 ^ b3, h2 = b1 ^ b2, h3 = b2 ^ b3;
    return (h0 << 3) | (h1 << 2) | (h2 << 1) | h3;
}

using u64 = unsigned long long;

__device__ __forceinline__ u64 f2pack(float lo, float hi) {
    u64 r; asm("mov.b64 %0, {%1, %2};" : "=l"(r) : "f"(lo), "f"(hi)); return r;
}
__device__ __forceinline__ void f2unpack(float& lo, float& hi, u64 v) {
    asm("mov.b64 {%0, %1}, %2;" : "=f"(lo), "=f"(hi) : "l"(v));
}
__device__ __forceinline__ u64 fma2(u64 a, u64 b, u64 c) {
    u64 d; asm("fma.rn.f32x2 %0, %1, %2, %3;" : "=l"(d) : "l"(a), "l"(b), "l"(c)); return d;
}
__device__ __forceinline__ u64 mul2(u64 a, u64 b) {
    u64 d; asm("mul.rn.f32x2 %0, %1, %2;" : "=l"(d) : "l"(a), "l"(b)); return d;
}
__device__ __forceinline__ u64 add2(u64 a, u64 b) {
    u64 d; asm("add.rn.f32x2 %0, %1, %2;" : "=l"(d) : "l"(a), "l"(b)); return d;
}
__device__ __forceinline__ u64 sub2(u64 a, u64 b) {
    u64 d; asm("sub.rn.f32x2 %0, %1, %2;" : "=l"(d) : "l"(a), "l"(b)); return d;
}

__global__ __launch_bounds__(256)
void quan2d_kernel(const float* __restrict__ x,
                   const float* __restrict__ w8,
                   float* __restrict__ out)
{
    // Packed per-gate constants: (c,c), (s,s), (-s,-s)
    __shared__ u64 Kc[8], Ks[8], Kn[8];
    if (threadIdx.x < 8) {
        float sv, cv;
        sincosf(0.5f * w8[threadIdx.x], &sv, &cv);
        Kc[threadIdx.x] = f2pack(cv, cv);
        Ks[threadIdx.x] = f2pack(sv, sv);
        Kn[threadIdx.x] = f2pack(-sv, -sv);
    }
    __syncthreads();

    const int tid = threadIdx.x;
    const int b   = blockIdx.x * 2 + (tid >> 7);  // image index
    const int t7  = tid & 127;
    const int pr  = t7 >> 3;        // patch row 0..15
    const int k   = t7 & 7;         // column-pair index; patches pc=2k, 2k+1
    const float* img = x + (size_t)b * 1024;

    // --- load + pack: rows 2pr..2pr+3, cols 4k..4k+5 (zero-pad r>=32, c>=32) ---
    // patch0 (pc=2k):   cols 4k..4k+3  = F.x F.y F.z F.w
    // patch1 (pc=2k+1): cols 4k+2..4k+5 = F.z F.w G.x G.y
    u64 a[16];
    #pragma unroll
    for (int i = 0; i < 4; i++) {
        const int r = 2 * pr + i;
        const bool rok = (r < 32);
        const float* base = img + r * 32 + 4 * k;
        float4 F = rok ? __ldg((const float4*)base) : make_float4(0.f, 0.f, 0.f, 0.f);
        float2 G = (rok && k < 7) ? __ldg((const float2*)(base + 4)) : make_float2(0.f, 0.f);
        a[4 * i + 0] = f2pack(F.x, F.z);
        a[4 * i + 1] = f2pack(F.y, F.w);
        a[4 * i + 2] = f2pack(F.z, G.x);
        a[4 * i + 3] = f2pack(F.w, G.y);
    }

    // --- RY layer 1: gate g acts on bit (8 >> g) ---
    #pragma unroll
    for (int g = 0; g < 4; g++) {
        const u64 c2 = Kc[g], s2 = Ks[g], n2 = Kn[g];
        const int BIT = 8 >> g;
        #pragma unroll
        for (int lo = 0; lo < 16; lo++) {
            if (lo & BIT) continue;
            const u64 xx = a[lo], yy = a[lo | BIT];
            a[lo]       = fma2(c2, xx, mul2(n2, yy));
            a[lo | BIT] = fma2(s2, xx, mul2(c2, yy));
        }
    }

    // --- CNOT ring: compile-time register permutation ---
    u64 t[16];
    #pragma unroll
    for (int s = 0; s < 16; s++) t[s] = a[permIdx(s)];

    // --- RY layer 2 ---
    #pragma unroll
    for (int g = 0; g < 4; g++) {
        const u64 c2 = Kc[4 + g], s2 = Ks[4 + g], n2 = Kn[4 + g];
        const int BIT = 8 >> g;
        #pragma unroll
        for (int lo = 0; lo < 16; lo++) {
            if (lo & BIT) continue;
            const u64 xx = t[lo], yy = t[lo | BIT];
            t[lo]       = fma2(c2, xx, mul2(n2, yy));
            t[lo | BIT] = fma2(s2, xx, mul2(c2, yy));
        }
    }

    // --- probabilities + signed-sum butterfly (all packed) ---
    u64 q[16];
    #pragma unroll
    for (int s = 0; s < 16; s++) q[s] = mul2(t[s], t[s]);

    // bit0 (value 1) -> wire 3
    u64 s1[8], e3 = sub2(q[0], q[1]);
    #pragma unroll
    for (int kk = 0; kk < 8; kk++) {
        s1[kk] = add2(q[2 * kk], q[2 * kk + 1]);
        if (kk) e3 = add2(e3, sub2(q[2 * kk], q[2 * kk + 1]));
    }
    // bit1 (value 2) -> wire 2
    u64 s2a[4], e2 = sub2(s1[0], s1[1]);
    #pragma unroll
    for (int kk = 0; kk < 4; kk++) {
        s2a[kk] = add2(s1[2 * kk], s1[2 * kk + 1]);
        if (kk) e2 = add2(e2, sub2(s1[2 * kk], s1[2 * kk + 1]));
    }
    // bit2 (value 4) -> wire 1
    const u64 s3a = add2(s2a[0], s2a[1]);
    const u64 s3b = add2(s2a[2], s2a[3]);
    const u64 e1  = add2(sub2(s2a[0], s2a[1]), sub2(s2a[2], s2a[3]));
    // bit3 (value 8) -> wire 0
    const u64 nrm = add2(s3a, s3b);
    const u64 e0  = sub2(s3a, s3b);

    // --- epilogue: unpack, reciprocal, scale, store both patches ---
    float n0, n1; f2unpack(n0, n1, nrm);
    const float r0 = __frcp_rn(n0);
    const float r1 = __frcp_rn(n1);

    float e0a, e0b, e1a, e1b, e2a, e2b, e3a, e3b;
    f2unpack(e0a, e0b, e0);
    f2unpack(e1a, e1b, e1);
    f2unpack(e2a, e2b, e2);
    f2unpack(e3a, e3b, e3);

    float4 o0 = make_float4(e0a * r0, e1a * r0, e2a * r0, e3a * r0);
    float4 o1 = make_float4(e0b * r1, e1b * r1, e2b * r1, e3b * r1);

    float4* op = (float4*)out + (size_t)b * 256 + pr * 16 + 2 * k;
    op[0] = o0;
    op[1] = o1;
}

extern "C" void kernel_launch(void* const* d_in, const int* in_sizes, int n_in,
                              void* d_out, int out_size)
{
    const float* x = (const float*)d_in[0];   // [B,1,32,32] fp32
    const float* w = (const float*)d_in[1];   // [1,8] fp32
    const int B = in_sizes[0] / 1024;
    quan2d_kernel<<<B / 2, 256>>>(x, w, (float*)d_out);
}

// round 3
// speedup vs baseline: 1.3352x; 1.1919x over previous
#include <cuda_runtime.h>
#include <cstdint>

// Quan2d, round 3: packed f32x2 + tangent-form RY gates.
// RY(th) = c*[[1,-t],[t,1]], t = tan(th/2). The uniform factor Prod(c_g)
// scales the whole statevector and cancels in <Z_w> = sum(+-u^2)/sum(u^2),
// so each gate pair costs 2 fmas instead of 4 fma-class ops.
// Two horizontally adjacent patches (pc=2k,2k+1) share lanes of each f32x2.
// CNOT ring permutation h: {0,13,3,14,6,11,5,8,12,1,15,2,10,7,9,4}.

__host__ __device__ constexpr int permIdx(int s) {
    int b0 = (s >> 3) & 1, b1 = (s >> 2) & 1, b2 = (s >> 1) & 1, b3 = s & 1;
    int h0 = b0 ^ b3, h1 = b0 ^ b1 ^ b3, h2 = b1 ^ b2, h3 = b2 ^ b3;
    return (h0 << 3) | (h1 << 2) | (h2 << 1) | h3;
}

using u64 = unsigned long long;

__device__ __forceinline__ u64 f2pack(float lo, float hi) {
    u64 r; asm("mov.b64 %0, {%1, %2};" : "=l"(r) : "f"(lo), "f"(hi)); return r;
}
__device__ __forceinline__ void f2unpack(float& lo, float& hi, u64 v) {
    asm("mov.b64 {%0, %1}, %2;" : "=f"(lo), "=f"(hi) : "l"(v));
}
__device__ __forceinline__ u64 fma2(u64 a, u64 b, u64 c) {
    u64 d; asm("fma.rn.f32x2 %0, %1, %2, %3;" : "=l"(d) : "l"(a), "l"(b), "l"(c)); return d;
}
__device__ __forceinline__ u64 mul2(u64 a, u64 b) {
    u64 d; asm("mul.rn.f32x2 %0, %1, %2;" : "=l"(d) : "l"(a), "l"(b)); return d;
}
__device__ __forceinline__ u64 add2(u64 a, u64 b) {
    u64 d; asm("add.rn.f32x2 %0, %1, %2;" : "=l"(d) : "l"(a), "l"(b)); return d;
}
__device__ __forceinline__ u64 sub2(u64 a, u64 b) {
    u64 d; asm("sub.rn.f32x2 %0, %1, %2;" : "=l"(d) : "l"(a), "l"(b)); return d;
}

__global__ __launch_bounds__(256, 5)
void quan2d_kernel(const float* __restrict__ x,
                   const float* __restrict__ w8,
                   float* __restrict__ out)
{
    // Packed per-gate tangents: (t,t) and (-t,-t)
    __shared__ u64 Kt[8], Kn[8];
    if (threadIdx.x < 8) {
        float sv, cv;
        sincosf(0.5f * w8[threadIdx.x], &sv, &cv);
        const float t = sv / cv;
        Kt[threadIdx.x] = f2pack(t, t);
        Kn[threadIdx.x] = f2pack(-t, -t);
    }
    __syncthreads();

    const int tid = threadIdx.x;
    const int b   = blockIdx.x * 2 + (tid >> 7);  // image index
    const int t7  = tid & 127;
    const int pr  = t7 >> 3;        // patch row 0..15
    const int k   = t7 & 7;         // column-pair index; patches pc=2k, 2k+1
    const float* img = x + (size_t)b * 1024;

    // --- load + pack: rows 2pr..2pr+3, cols 4k..4k+5 (zero-pad r>=32, c>=32) ---
    u64 a[16];
    #pragma unroll
    for (int i = 0; i < 4; i++) {
        const int r = 2 * pr + i;
        const bool rok = (r < 32);
        const float* base = img + r * 32 + 4 * k;
        float4 F = rok ? __ldg((const float4*)base) : make_float4(0.f, 0.f, 0.f, 0.f);
        float2 G = (rok && k < 7) ? __ldg((const float2*)(base + 4)) : make_float2(0.f, 0.f);
        a[4 * i + 0] = f2pack(F.x, F.z);
        a[4 * i + 1] = f2pack(F.y, F.w);
        a[4 * i + 2] = f2pack(F.z, G.x);
        a[4 * i + 3] = f2pack(F.w, G.y);
    }

    // --- RY layer 1 (tangent form): gate g acts on bit (8 >> g) ---
    #pragma unroll
    for (int g = 0; g < 4; g++) {
        const u64 tp = Kt[g], tn = Kn[g];
        const int BIT = 8 >> g;
        #pragma unroll
        for (int lo = 0; lo < 16; lo++) {
            if (lo & BIT) continue;
            const u64 xx = a[lo], yy = a[lo | BIT];
            a[lo]       = fma2(tn, yy, xx);
            a[lo | BIT] = fma2(tp, xx, yy);
        }
    }

    // --- CNOT ring: compile-time register permutation ---
    u64 t[16];
    #pragma unroll
    for (int s = 0; s < 16; s++) t[s] = a[permIdx(s)];

    // --- RY layer 2 (tangent form) ---
    #pragma unroll
    for (int g = 0; g < 4; g++) {
        const u64 tp = Kt[4 + g], tn = Kn[4 + g];
        const int BIT = 8 >> g;
        #pragma unroll
        for (int lo = 0; lo < 16; lo++) {
            if (lo & BIT) continue;
            const u64 xx = t[lo], yy = t[lo | BIT];
            t[lo]       = fma2(tn, yy, xx);
            t[lo | BIT] = fma2(tp, xx, yy);
        }
    }

    // --- probabilities + signed-sum butterfly (all packed) ---
    u64 q[16];
    #pragma unroll
    for (int s = 0; s < 16; s++) q[s] = mul2(t[s], t[s]);

    // bit0 (value 1) -> wire 3
    u64 s1[8], e3 = sub2(q[0], q[1]);
    #pragma unroll
    for (int kk = 0; kk < 8; kk++) {
        s1[kk] = add2(q[2 * kk], q[2 * kk + 1]);
        if (kk) e3 = add2(e3, sub2(q[2 * kk], q[2 * kk + 1]));
    }
    // bit1 (value 2) -> wire 2
    u64 s2a[4], e2 = sub2(s1[0], s1[1]);
    #pragma unroll
    for (int kk = 0; kk < 4; kk++) {
        s2a[kk] = add2(s1[2 * kk], s1[2 * kk + 1]);
        if (kk) e2 = add2(e2, sub2(s1[2 * kk], s1[2 * kk + 1]));
    }
    // bit2 (value 4) -> wire 1
    const u64 s3a = add2(s2a[0], s2a[1]);
    const u64 s3b = add2(s2a[2], s2a[3]);
    const u64 e1  = add2(sub2(s2a[0], s2a[1]), sub2(s2a[2], s2a[3]));
    // bit3 (value 8) -> wire 0
    const u64 nrm = add2(s3a, s3b);
    const u64 e0  = sub2(s3a, s3b);

    // --- epilogue: unpack, reciprocal, scale, store both patches ---
    float n0, n1; f2unpack(n0, n1, nrm);
    const float r0 = __frcp_rn(n0);
    const float r1 = __frcp_rn(n1);

    float e0a, e0b, e1a, e1b, e2a, e2b, e3a, e3b;
    f2unpack(e0a, e0b, e0);
    f2unpack(e1a, e1b, e1);
    f2unpack(e2a, e2b, e2);
    f2unpack(e3a, e3b, e3);

    float4 o0 = make_float4(e0a * r0, e1a * r0, e2a * r0, e3a * r0);
    float4 o1 = make_float4(e0b * r1, e1b * r1, e2b * r1, e3b * r1);

    float4* op = (float4*)out + (size_t)b * 256 + pr * 16 + 2 * k;
    op[0] = o0;
    op[1] = o1;
}

extern "C" void kernel_launch(void* const* d_in, const int* in_sizes, int n_in,
                              void* d_out, int out_size)
{
    const float* x = (const float*)d_in[0];   // [B,1,32,32] fp32
    const float* w = (const float*)d_in[1];   // [1,8] fp32
    const int B = in_sizes[0] / 1024;
    quan2d_kernel<<<B / 2, 256>>>(x, w, (float*)d_out);
}

// round 4
// speedup vs baseline: 1.4679x; 1.0994x over previous
#include <cuda_runtime.h>

// Quan2d, round 4: scalar tangent-form gates + 2S-n reduction.
//
// RY(th) = cos(th/2) * [[1,-t],[t,1]], t = tan(th/2). Uniform scalars cancel
// in <Z_w> = sum(+-u^2)/sum(u^2), so each gate pair costs 2 FFMA.
// <Z_w> = 2*S_w/n - 1 where S_w = sum over states with bit_w = 0 of u^2,
// n = sum of all u^2. The binary tree that computes n provides S_w for
// wires 0..2 nearly free; wire 3 needs one extra 8-way sum.
//
// CNOT ring permutation h (new[s] = old[h(s)]):
// {0,13,3,14,6,11,5,8,12,1,15,2,10,7,9,4}.

__host__ __device__ constexpr int permIdx(int s) {
    int b0 = (s >> 3) & 1, b1 = (s >> 2) & 1, b2 = (s >> 1) & 1, b3 = s & 1;
    int h0 = b0 ^ b3, h1 = b0 ^ b1 ^ b3, h2 = b1 ^ b2, h3 = b2 ^ b3;
    return (h0 << 3) | (h1 << 2) | (h2 << 1) | h3;
}

__global__ __launch_bounds__(256)
void quan2d_kernel(const float* __restrict__ x,
                   const float* __restrict__ w8,
                   float* __restrict__ out)
{
    // per-gate tangents
    __shared__ float ct[8];
    if (threadIdx.x < 8) {
        float sv, cv;
        sincosf(0.5f * w8[threadIdx.x], &sv, &cv);
        ct[threadIdx.x] = sv / cv;
    }
    __syncthreads();

    const int b  = blockIdx.x;
    const int pr = threadIdx.x >> 4;   // patch row 0..15
    const int pc = threadIdx.x & 15;   // patch col 0..15
    const float* img = x + (size_t)b * 1024;

    // --- load 4x4 patch (row-major), zero-padded at rows/cols >= 32 ---
    float a[16];
    #pragma unroll
    for (int i = 0; i < 4; i++) {
        const int r = pr * 2 + i;
        const bool rok = (r < 32);
        const float2* rowp = (const float2*)(img + r * 32 + pc * 2);
        float2 A = rok ? __ldg(rowp) : make_float2(0.f, 0.f);
        float2 B = (rok && pc < 15) ? __ldg(rowp + 1) : make_float2(0.f, 0.f);
        a[4 * i + 0] = A.x;
        a[4 * i + 1] = A.y;
        a[4 * i + 2] = B.x;
        a[4 * i + 3] = B.y;
    }

    // --- RY layer 1 (tangent form): gate g acts on bit (8 >> g) ---
    #pragma unroll
    for (int g = 0; g < 4; g++) {
        const float tg = ct[g];
        const int BIT = 8 >> g;
        #pragma unroll
        for (int lo = 0; lo < 16; lo++) {
            if (lo & BIT) continue;
            const float xx = a[lo], yy = a[lo | BIT];
            a[lo]       = fmaf(-tg, yy, xx);
            a[lo | BIT] = fmaf( tg, xx, yy);
        }
    }

    // --- CNOT ring: compile-time register permutation ---
    float t[16];
    #pragma unroll
    for (int s = 0; s < 16; s++) t[s] = a[permIdx(s)];

    // --- RY layer 2 (tangent form) ---
    #pragma unroll
    for (int g = 0; g < 4; g++) {
        const float tg = ct[4 + g];
        const int BIT = 8 >> g;
        #pragma unroll
        for (int lo = 0; lo < 16; lo++) {
            if (lo & BIT) continue;
            const float xx = t[lo], yy = t[lo | BIT];
            t[lo]       = fmaf(-tg, yy, xx);
            t[lo | BIT] = fmaf( tg, xx, yy);
        }
    }

    // --- probabilities ---
    float q[16];
    #pragma unroll
    for (int s = 0; s < 16; s++) q[s] = t[s] * t[s];

    // --- tree sum for n, harvesting S_w along the way ---
    // level 1: pair over bit0 (value 1)
    float s1[8];
    #pragma unroll
    for (int k = 0; k < 8; k++) s1[k] = q[2 * k] + q[2 * k + 1];
    // level 2: pair over bit1 (value 2)
    float s2[4];
    #pragma unroll
    for (int k = 0; k < 4; k++) s2[k] = s1[2 * k] + s1[2 * k + 1];
    // level 3: pair over bit2 (value 4)
    const float s3a = s2[0] + s2[1];
    const float s3b = s2[2] + s2[3];
    const float n   = s3a + s3b;

    // S_w = sum of q over states with the wire-w bit == 0
    // wire 0 <-> bit3 (value 8): S0 = s3a
    const float S0 = s3a;
    // wire 1 <-> bit2 (value 4): S1 = s2[0] + s2[2]
    const float S1 = s2[0] + s2[2];
    // wire 2 <-> bit1 (value 2): S2 = s1[0] + s1[2] + s1[4] + s1[6]
    const float S2 = (s1[0] + s1[2]) + (s1[4] + s1[6]);
    // wire 3 <-> bit0 (value 1): S3 = sum of q[even]
    const float S3 = ((q[0] + q[2]) + (q[4] + q[6])) + ((q[8] + q[10]) + (q[12] + q[14]));

    // --- epilogue: <Z_w> = 2*S_w/n - 1 ---
    const float r2 = 2.0f * __frcp_rn(n);
    float4 o;
    o.x = fmaf(S0, r2, -1.0f);
    o.y = fmaf(S1, r2, -1.0f);
    o.z = fmaf(S2, r2, -1.0f);
    o.w = fmaf(S3, r2, -1.0f);
    ((float4*)out)[(size_t)b * 256 + threadIdx.x] = o;
}

extern "C" void kernel_launch(void* const* d_in, const int* in_sizes, int n_in,
                              void* d_out, int out_size)
{
    const float* x = (const float*)d_in[0];   // [B,1,32,32] fp32
    const float* w = (const float*)d_in[1];   // [1,8] fp32
    const int B = in_sizes[0] / 1024;
    quan2d_kernel<<<B, 256>>>(x, w, (float*)d_out);
}